// round 1
// baseline (speedup 1.0000x reference)
#include <cuda_runtime.h>

#define NU 100000
#define NI 50000
#define NN 150000          // NU + NI
#define NE 4800000
#define EMB 64
#define NF4 (NN * (EMB/4)) // float4 elements per node buffer = 2,400,000
#define UF4 (NU * (EMB/4)) // user float4 count = 1,600,000

// Ping-pong node-embedding buffers (38.4 MB each). Device globals: the only
// legal scratch under the allocation guards.
__device__ float4 g_bufA[NF4];
__device__ float4 g_bufB[NF4];

__device__ __forceinline__ void red_add_v4(float4* p, float4 v) {
    asm volatile("red.global.add.v4.f32 [%0], {%1, %2, %3, %4};"
                 :: "l"(p), "f"(v.x), "f"(v.y), "f"(v.z), "f"(v.w)
                 : "memory");
}

// out = ego, bufA = ego, bufB = 0
__global__ void k_init(const float4* __restrict__ ue,
                       const float4* __restrict__ ie,
                       float4* __restrict__ out) {
    int i = blockIdx.x * blockDim.x + threadIdx.x;
    if (i >= NF4) return;
    float4 v = (i < UF4) ? __ldg(ue + i) : __ldg(ie + (i - UF4));
    out[i]    = v;
    g_bufA[i] = v;
    g_bufB[i] = make_float4(0.f, 0.f, 0.f, 0.f);
}

// Scatter SpMM: y[dst] += w * x[src].  16 threads per edge, float4 per thread.
// ab = 0: x = A, y = B;  ab = 1: x = B, y = A.
__global__ void k_spmm(const int*   __restrict__ src,
                       const int*   __restrict__ dst,
                       const float* __restrict__ w,
                       int ab) {
    const float4* __restrict__ x = ab ? g_bufB : g_bufA;
    float4*                    y = ab ? g_bufA : g_bufB;

    unsigned long long tid = (unsigned long long)blockIdx.x * blockDim.x + threadIdx.x;
    unsigned e = (unsigned)(tid >> 4);
    unsigned c = (unsigned)(tid & 15u);
    if (e >= NE) return;

    int   s  = __ldg(src + e);
    int   d  = __ldg(dst + e);
    float wt = __ldg(w + e);

    float4 v = __ldg(x + (unsigned)s * 16u + c);
    float4 m = make_float4(v.x * wt, v.y * wt, v.z * wt, v.w * wt);
    red_add_v4(y + (unsigned)d * 16u + c, m);
}

// acc += y ; zero the other buffer (it becomes the next spmm destination).
// ab = 0: y = B, zero A;  ab = 1: y = A, zero B.
__global__ void k_acc_zero(float4* __restrict__ out, int ab) {
    int i = blockIdx.x * blockDim.x + threadIdx.x;
    if (i >= NF4) return;
    const float4* y  = ab ? g_bufA : g_bufB;
    float4*       xz = ab ? g_bufB : g_bufA;
    float4 o = out[i];
    float4 v = y[i];
    o.x += v.x; o.y += v.y; o.z += v.z; o.w += v.w;
    out[i] = o;
    xz[i]  = make_float4(0.f, 0.f, 0.f, 0.f);
}

// out = (out + bufB) * 0.25   (final layer output lives in B)
__global__ void k_final(float4* __restrict__ out) {
    int i = blockIdx.x * blockDim.x + threadIdx.x;
    if (i >= NF4) return;
    float4 o = out[i];
    float4 v = g_bufB[i];
    o.x = (o.x + v.x) * 0.25f;
    o.y = (o.y + v.y) * 0.25f;
    o.z = (o.z + v.z) * 0.25f;
    o.w = (o.w + v.w) * 0.25f;
    out[i] = o;
}

extern "C" void kernel_launch(void* const* d_in, const int* in_sizes, int n_in,
                              void* d_out, int out_size) {
    const float4* ue  = (const float4*)d_in[0];   // user_emb  [100000, 64] f32
    const float4* ie  = (const float4*)d_in[1];   // item_emb  [50000, 64]  f32
    const float*  w   = (const float*) d_in[2];   // edge_weight [4.8M] f32
    const int*    src = (const int*)   d_in[3];   // edge_src [4.8M] i32
    const int*    dst = (const int*)   d_in[4];   // edge_dst [4.8M] i32
    float4*       out = (float4*)d_out;

    const int TB = 256;
    const int gElem = (NF4 + TB - 1) / TB;                       // 9375 blocks
    const long long spmmThreads = (long long)NE * 16;
    const int gSpmm = (int)((spmmThreads + TB - 1) / TB);        // 300000 blocks

    // out = ego, A = ego, B = 0
    k_init<<<gElem, TB>>>(ue, ie, out);

    // layer 1: A -> B ; out += B ; zero A
    k_spmm<<<gSpmm, TB>>>(src, dst, w, 0);
    k_acc_zero<<<gElem, TB>>>(out, 0);

    // layer 2: B -> A ; out += A ; zero B
    k_spmm<<<gSpmm, TB>>>(src, dst, w, 1);
    k_acc_zero<<<gElem, TB>>>(out, 1);

    // layer 3: A -> B ; out = (out + B)/4
    k_spmm<<<gSpmm, TB>>>(src, dst, w, 0);
    k_final<<<gElem, TB>>>(out);
}

// round 2
// speedup vs baseline: 1.3126x; 1.3126x over previous
#include <cuda_runtime.h>

#define NU 100000
#define NI 50000
#define NN 150000          // NU + NI
#define NE 4800000
#define EMB 64
#define NF4 (NN * (EMB/4)) // float4 elements per node buffer = 2,400,000
#define UF4 (NU * (EMB/4)) // user float4 count = 1,600,000

// SpMM launch geometry: 8 lanes per edge, 2 float4 per lane.
#define TBS 256
#define SLOTS (TBS / 8)        // 32 edges concurrently per block
#define UNROLL 4
#define EPB (SLOTS * UNROLL)   // 128 edges per block; 4.8M % 128 == 0
#define GSPMM (NE / EPB)       // 37500 blocks

// Ping-pong node-embedding buffers (38.4 MB each). Device globals: the only
// legal scratch under the allocation guards.
__device__ float4 g_bufA[NF4];
__device__ float4 g_bufB[NF4];

__device__ __forceinline__ void red_add_v4(float4* p, float4 v) {
    asm volatile("red.global.add.v4.f32 [%0], {%1, %2, %3, %4};"
                 :: "l"(p), "f"(v.x), "f"(v.y), "f"(v.z), "f"(v.w)
                 : "memory");
}

// out = ego, bufA = ego, bufB = 0
__global__ void k_init(const float4* __restrict__ ue,
                       const float4* __restrict__ ie,
                       float4* __restrict__ out) {
    int i = blockIdx.x * blockDim.x + threadIdx.x;
    if (i >= NF4) return;
    float4 v = (i < UF4) ? __ldg(ue + i) : __ldg(ie + (i - UF4));
    out[i]    = v;
    g_bufA[i] = v;
    g_bufB[i] = make_float4(0.f, 0.f, 0.f, 0.f);
}

// Scatter SpMM: y[dst] += w * x[src].
// 8 lanes per edge; lane c handles float4 c and c+8 of the 16-float4 row.
// 4 independent edges per thread (unrolled) -> front-batched loads, high MLP.
// ab = 0: x = A, y = B;  ab = 1: x = B, y = A.
__global__ void __launch_bounds__(TBS) k_spmm(const int*   __restrict__ src,
                                              const int*   __restrict__ dst,
                                              const float* __restrict__ w,
                                              int ab) {
    const float4* __restrict__ x = ab ? g_bufB : g_bufA;
    float4*                    y = ab ? g_bufA : g_bufB;

    const unsigned slot = threadIdx.x >> 3;   // 0..31
    const unsigned c    = threadIdx.x & 7u;   // 0..7
    const unsigned ebase = blockIdx.x * (unsigned)EPB + slot;

    #pragma unroll
    for (int u = 0; u < UNROLL; u++) {
        const unsigned e = ebase + u * SLOTS;   // always < NE (exact tiling)
        const int   s  = __ldg(src + e);
        const int   d  = __ldg(dst + e);
        const float wt = __ldg(w + e);

        const float4* __restrict__ xp = x + (unsigned)s * 16u + c;
        float4 v0 = __ldg(xp);
        float4 v1 = __ldg(xp + 8);

        float4* yp = y + (unsigned)d * 16u + c;
        red_add_v4(yp,     make_float4(v0.x * wt, v0.y * wt, v0.z * wt, v0.w * wt));
        red_add_v4(yp + 8, make_float4(v1.x * wt, v1.y * wt, v1.z * wt, v1.w * wt));
    }
}

// acc += y ; zero the other buffer (it becomes the next spmm destination).
// ab = 0: y = B, zero A;  ab = 1: y = A, zero B.
__global__ void k_acc_zero(float4* __restrict__ out, int ab) {
    int i = blockIdx.x * blockDim.x + threadIdx.x;
    if (i >= NF4) return;
    const float4* y  = ab ? g_bufA : g_bufB;
    float4*       xz = ab ? g_bufB : g_bufA;
    float4 o = out[i];
    float4 v = y[i];
    o.x += v.x; o.y += v.y; o.z += v.z; o.w += v.w;
    out[i] = o;
    xz[i]  = make_float4(0.f, 0.f, 0.f, 0.f);
}

// out = (out + bufB) * 0.25   (final layer output lives in B)
__global__ void k_final(float4* __restrict__ out) {
    int i = blockIdx.x * blockDim.x + threadIdx.x;
    if (i >= NF4) return;
    float4 o = out[i];
    float4 v = g_bufB[i];
    o.x = (o.x + v.x) * 0.25f;
    o.y = (o.y + v.y) * 0.25f;
    o.z = (o.z + v.z) * 0.25f;
    o.w = (o.w + v.w) * 0.25f;
    out[i] = o;
}

extern "C" void kernel_launch(void* const* d_in, const int* in_sizes, int n_in,
                              void* d_out, int out_size) {
    const float4* ue  = (const float4*)d_in[0];   // user_emb  [100000, 64] f32
    const float4* ie  = (const float4*)d_in[1];   // item_emb  [50000, 64]  f32
    const float*  w   = (const float*) d_in[2];   // edge_weight [4.8M] f32
    const int*    src = (const int*)   d_in[3];   // edge_src [4.8M] i32
    const int*    dst = (const int*)   d_in[4];   // edge_dst [4.8M] i32
    float4*       out = (float4*)d_out;

    const int TB = 256;
    const int gElem = (NF4 + TB - 1) / TB;        // 9375 blocks

    // out = ego, A = ego, B = 0
    k_init<<<gElem, TB>>>(ue, ie, out);

    // layer 1: A -> B ; out += B ; zero A
    k_spmm<<<GSPMM, TBS>>>(src, dst, w, 0);
    k_acc_zero<<<gElem, TB>>>(out, 0);

    // layer 2: B -> A ; out += A ; zero B
    k_spmm<<<GSPMM, TBS>>>(src, dst, w, 1);
    k_acc_zero<<<gElem, TB>>>(out, 1);

    // layer 3: A -> B ; out = (out + B)/4
    k_spmm<<<GSPMM, TBS>>>(src, dst, w, 0);
    k_final<<<gElem, TB>>>(out);
}

// round 3
// speedup vs baseline: 2.2773x; 1.7349x over previous
#include <cuda_runtime.h>

#define NU 100000
#define NI 50000
#define NN 150000            // NU + NI
#define NE 4800000
#define NF4 (NN * 16)        // float4 per node buffer = 2,400,000
#define UF4 (NU * 16)

#define SCAN_BS 1024
#define NB ((NN + SCAN_BS - 1) / SCAN_BS)   // 147 scan blocks

// Device-global scratch (allocation rules forbid cudaMalloc).
__device__ float4 g_bufA[NF4];      // ping-pong embedding buffers
__device__ float4 g_bufB[NF4];
__device__ int    g_deg[NN];        // in-degree histogram
__device__ int    g_off[NN + 1];    // CSR row offsets (exclusive scan)
__device__ int    g_cursor[NN];     // atomic fill cursors
__device__ int    g_sums[NB];       // per-scan-block totals
__device__ int    g_sumx[NB];       // exclusive scan of block totals
__device__ int    g_csr_src[NE];    // CSR: source node per incoming edge
__device__ float  g_csr_w[NE];      // CSR: weight per incoming edge

// ---------------------------------------------------------------- init
// out = ego, bufA = ego; zero the degree histogram (fresh every replay).
__global__ void k_init(const float4* __restrict__ ue,
                       const float4* __restrict__ ie,
                       float4* __restrict__ out) {
    int i = blockIdx.x * blockDim.x + threadIdx.x;
    if (i < NN) g_deg[i] = 0;
    if (i >= NF4) return;
    float4 v = (i < UF4) ? __ldg(ue + i) : __ldg(ie + (i - UF4));
    out[i]    = v;
    g_bufA[i] = v;
}

// ---------------------------------------------------------------- CSR build
__global__ void k_hist(const int* __restrict__ dst) {
    int e = blockIdx.x * blockDim.x + threadIdx.x;
    if (e < NE) atomicAdd(&g_deg[__ldg(dst + e)], 1);
}

// Block-local exclusive scan of g_deg into g_off; block totals into g_sums.
__global__ void k_scan_part() {
    __shared__ int sh[SCAN_BS];
    int t = threadIdx.x;
    int i = blockIdx.x * SCAN_BS + t;
    int v = (i < NN) ? g_deg[i] : 0;
    sh[t] = v;
    __syncthreads();
    #pragma unroll
    for (int ofs = 1; ofs < SCAN_BS; ofs <<= 1) {
        int add = (t >= ofs) ? sh[t - ofs] : 0;
        __syncthreads();
        sh[t] += add;
        __syncthreads();
    }
    if (i < NN) g_off[i] = sh[t] - v;              // exclusive
    if (t == SCAN_BS - 1) g_sums[blockIdx.x] = sh[t];
}

// Tiny sequential exclusive scan of 147 block totals.
__global__ void k_scan_tops() {
    int run = 0;
    for (int b = 0; b < NB; b++) { g_sumx[b] = run; run += g_sums[b]; }
}

// Add block bases; initialize fill cursors; g_off[NN] = NE (known total).
__global__ void k_scan_add() {
    int i = blockIdx.x * blockDim.x + threadIdx.x;
    if (i >= NN) return;
    int o = g_off[i] + g_sumx[i >> 10];
    g_off[i]    = o;
    g_cursor[i] = o;
    if (i == 0) g_off[NN] = NE;
}

__global__ void k_fill(const int*   __restrict__ src,
                       const int*   __restrict__ dst,
                       const float* __restrict__ w) {
    int e = blockIdx.x * blockDim.x + threadIdx.x;
    if (e >= NE) return;
    int d = __ldg(dst + e);
    int p = atomicAdd(&g_cursor[d], 1);
    g_csr_src[p] = __ldg(src + e);
    g_csr_w[p]   = __ldg(w + e);
}

// ---------------------------------------------------------------- pull SpMM
// 16 threads per node, one float4 column each. Registers accumulate all
// incoming messages; single store. Fused: out += y ; final layer: out =
// (out + y) * 0.25 and y is not stored.
__global__ void __launch_bounds__(256) k_pull(float4* __restrict__ out,
                                              int ab, int final_layer) {
    int t    = blockIdx.x * blockDim.x + threadIdx.x;   // == node*16 + c
    int node = t >> 4;
    int c    = t & 15;
    const float4* __restrict__ x = ab ? g_bufB : g_bufA;
    float4*                    y = ab ? g_bufA : g_bufB;

    int i   = g_off[node];
    int end = g_off[node + 1];
    float4 acc = make_float4(0.f, 0.f, 0.f, 0.f);

    // 4 independent edges in flight per iteration.
    for (; i + 4 <= end; i += 4) {
        int   s0 = __ldg(g_csr_src + i);
        int   s1 = __ldg(g_csr_src + i + 1);
        int   s2 = __ldg(g_csr_src + i + 2);
        int   s3 = __ldg(g_csr_src + i + 3);
        float w0 = __ldg(g_csr_w + i);
        float w1 = __ldg(g_csr_w + i + 1);
        float w2 = __ldg(g_csr_w + i + 2);
        float w3 = __ldg(g_csr_w + i + 3);
        float4 v0 = __ldg(x + s0 * 16 + c);
        float4 v1 = __ldg(x + s1 * 16 + c);
        float4 v2 = __ldg(x + s2 * 16 + c);
        float4 v3 = __ldg(x + s3 * 16 + c);
        acc.x += w0 * v0.x; acc.y += w0 * v0.y; acc.z += w0 * v0.z; acc.w += w0 * v0.w;
        acc.x += w1 * v1.x; acc.y += w1 * v1.y; acc.z += w1 * v1.z; acc.w += w1 * v1.w;
        acc.x += w2 * v2.x; acc.y += w2 * v2.y; acc.z += w2 * v2.z; acc.w += w2 * v2.w;
        acc.x += w3 * v3.x; acc.y += w3 * v3.y; acc.z += w3 * v3.z; acc.w += w3 * v3.w;
    }
    for (; i < end; i++) {
        int   s  = __ldg(g_csr_src + i);
        float wt = __ldg(g_csr_w + i);
        float4 v = __ldg(x + s * 16 + c);
        acc.x += wt * v.x; acc.y += wt * v.y; acc.z += wt * v.z; acc.w += wt * v.w;
    }

    if (!final_layer) y[t] = acc;

    float4 o = out[t];
    o.x += acc.x; o.y += acc.y; o.z += acc.z; o.w += acc.w;
    if (final_layer) { o.x *= 0.25f; o.y *= 0.25f; o.z *= 0.25f; o.w *= 0.25f; }
    out[t] = o;
}

// ---------------------------------------------------------------- launch
extern "C" void kernel_launch(void* const* d_in, const int* in_sizes, int n_in,
                              void* d_out, int out_size) {
    const float4* ue  = (const float4*)d_in[0];   // user_emb  [100000,64] f32
    const float4* ie  = (const float4*)d_in[1];   // item_emb  [50000,64]  f32
    const float*  w   = (const float*) d_in[2];   // edge_weight [4.8M] f32
    const int*    src = (const int*)   d_in[3];   // edge_src [4.8M] i32
    const int*    dst = (const int*)   d_in[4];   // edge_dst [4.8M] i32
    float4*       out = (float4*)d_out;

    const int TB     = 256;
    const int gElem  = (NF4 + TB - 1) / TB;   // 9375
    const int gEdge  = (NE  + TB - 1) / TB;   // 18750
    const int gNode  = (NN  + TB - 1) / TB;   // 586

    k_init<<<gElem, TB>>>(ue, ie, out);

    // CSR build (per replay; graph-captured)
    k_hist     <<<gEdge, TB>>>(dst);
    k_scan_part<<<NB, SCAN_BS>>>();
    k_scan_tops<<<1, 1>>>();
    k_scan_add <<<gNode, TB>>>();
    k_fill     <<<gEdge, TB>>>(src, dst, w);

    // 3 pull layers; acc and final scale fused into epilogues.
    k_pull<<<gElem, TB>>>(out, 0, 0);   // x=A -> y=B ; out += y
    k_pull<<<gElem, TB>>>(out, 1, 0);   // x=B -> y=A ; out += y
    k_pull<<<gElem, TB>>>(out, 0, 1);   // x=A -> (out + y)/4
}

// round 4
// speedup vs baseline: 2.3233x; 1.0202x over previous
#include <cuda_runtime.h>

#define NU 100000
#define NI 50000
#define NN 150000            // NU + NI
#define NE 4800000
#define NF4 (NN * 16)        // float4 per node buffer = 2,400,000
#define UF4 (NU * 16)

#define SCAN_BS 1024
#define NB ((NN + SCAN_BS - 1) / SCAN_BS)   // 147 scan blocks

// Device-global scratch (allocation rules forbid cudaMalloc).
__device__ float4 g_bufA[NF4];      // ping-pong embedding buffers
__device__ float4 g_bufB[NF4];
__device__ int    g_deg[NN];        // in-degree histogram
__device__ int    g_off[NN + 1];    // CSR row offsets (exclusive scan)
__device__ int    g_cursor[NN];     // atomic fill cursors
__device__ int    g_sums[NB];       // per-scan-block totals
__device__ int    g_sumx[NB];       // exclusive scan of block totals
__device__ int2   g_csr[NE];        // packed CSR: (src, weight bits) per edge

// ---------------------------------------------------------------- init
// out = ego, bufA = ego; zero the degree histogram (fresh every replay).
__global__ void k_init(const float4* __restrict__ ue,
                       const float4* __restrict__ ie,
                       float4* __restrict__ out) {
    int i = blockIdx.x * blockDim.x + threadIdx.x;
    if (i < NN) g_deg[i] = 0;
    if (i >= NF4) return;
    float4 v = (i < UF4) ? __ldg(ue + i) : __ldg(ie + (i - UF4));
    out[i]    = v;
    g_bufA[i] = v;
}

// ---------------------------------------------------------------- CSR build
__global__ void k_hist(const int* __restrict__ dst) {
    int e = blockIdx.x * blockDim.x + threadIdx.x;
    if (e < NE) atomicAdd(&g_deg[__ldg(dst + e)], 1);
}

// Block-local exclusive scan of g_deg into g_off; block totals into g_sums.
__global__ void k_scan_part() {
    __shared__ int sh[SCAN_BS];
    int t = threadIdx.x;
    int i = blockIdx.x * SCAN_BS + t;
    int v = (i < NN) ? g_deg[i] : 0;
    sh[t] = v;
    __syncthreads();
    #pragma unroll
    for (int ofs = 1; ofs < SCAN_BS; ofs <<= 1) {
        int add = (t >= ofs) ? sh[t - ofs] : 0;
        __syncthreads();
        sh[t] += add;
        __syncthreads();
    }
    if (i < NN) g_off[i] = sh[t] - v;              // exclusive
    if (t == SCAN_BS - 1) g_sums[blockIdx.x] = sh[t];
}

// Parallel exclusive scan of the 147 block totals (one 256-thread block).
__global__ void k_scan_tops() {
    __shared__ int sh[256];
    int t = threadIdx.x;
    int v = (t < NB) ? g_sums[t] : 0;
    sh[t] = v;
    __syncthreads();
    #pragma unroll
    for (int ofs = 1; ofs < 256; ofs <<= 1) {
        int add = (t >= ofs) ? sh[t - ofs] : 0;
        __syncthreads();
        sh[t] += add;
        __syncthreads();
    }
    if (t < NB) g_sumx[t] = sh[t] - v;             // exclusive
}

// Add block bases; initialize fill cursors; g_off[NN] = NE (known total).
__global__ void k_scan_add() {
    int i = blockIdx.x * blockDim.x + threadIdx.x;
    if (i >= NN) return;
    int o = g_off[i] + g_sumx[i >> 10];
    g_off[i]    = o;
    g_cursor[i] = o;
    if (i == 0) g_off[NN] = NE;
}

// Scatter edges into packed CSR slots: one 8-byte store per edge.
__global__ void k_fill(const int*   __restrict__ src,
                       const int*   __restrict__ dst,
                       const float* __restrict__ w) {
    int e = blockIdx.x * blockDim.x + threadIdx.x;
    if (e >= NE) return;
    int d = __ldg(dst + e);
    int p = atomicAdd(&g_cursor[d], 1);
    g_csr[p] = make_int2(__ldg(src + e), __float_as_int(__ldg(w + e)));
}

// ---------------------------------------------------------------- pull SpMM
// 16 threads per node, one float4 column each. Registers accumulate all
// incoming messages; single store. Fused: out += y ; final layer: out =
// (out + y) * 0.25 and y is not stored.
__global__ void __launch_bounds__(256) k_pull(float4* __restrict__ out,
                                              int ab, int final_layer) {
    int t    = blockIdx.x * blockDim.x + threadIdx.x;   // == node*16 + c
    int node = t >> 4;
    int c    = t & 15;
    const float4* __restrict__ x = ab ? g_bufB : g_bufA;
    float4*                    y = ab ? g_bufA : g_bufB;

    int i   = __ldg(g_off + node);
    int end = __ldg(g_off + node + 1);
    float4 acc = make_float4(0.f, 0.f, 0.f, 0.f);

    // 4 independent edges in flight per iteration; packed (src, w) loads.
    for (; i + 4 <= end; i += 4) {
        int2 p0 = __ldg(g_csr + i);
        int2 p1 = __ldg(g_csr + i + 1);
        int2 p2 = __ldg(g_csr + i + 2);
        int2 p3 = __ldg(g_csr + i + 3);
        float4 v0 = __ldg(x + p0.x * 16 + c);
        float4 v1 = __ldg(x + p1.x * 16 + c);
        float4 v2 = __ldg(x + p2.x * 16 + c);
        float4 v3 = __ldg(x + p3.x * 16 + c);
        float w0 = __int_as_float(p0.y);
        float w1 = __int_as_float(p1.y);
        float w2 = __int_as_float(p2.y);
        float w3 = __int_as_float(p3.y);
        acc.x += w0 * v0.x; acc.y += w0 * v0.y; acc.z += w0 * v0.z; acc.w += w0 * v0.w;
        acc.x += w1 * v1.x; acc.y += w1 * v1.y; acc.z += w1 * v1.z; acc.w += w1 * v1.w;
        acc.x += w2 * v2.x; acc.y += w2 * v2.y; acc.z += w2 * v2.z; acc.w += w2 * v2.w;
        acc.x += w3 * v3.x; acc.y += w3 * v3.y; acc.z += w3 * v3.z; acc.w += w3 * v3.w;
    }
    for (; i < end; i++) {
        int2 p = __ldg(g_csr + i);
        float4 v = __ldg(x + p.x * 16 + c);
        float wt = __int_as_float(p.y);
        acc.x += wt * v.x; acc.y += wt * v.y; acc.z += wt * v.z; acc.w += wt * v.w;
    }

    if (!final_layer) y[t] = acc;

    float4 o = out[t];
    o.x += acc.x; o.y += acc.y; o.z += acc.z; o.w += acc.w;
    if (final_layer) { o.x *= 0.25f; o.y *= 0.25f; o.z *= 0.25f; o.w *= 0.25f; }
    out[t] = o;
}

// ---------------------------------------------------------------- launch
extern "C" void kernel_launch(void* const* d_in, const int* in_sizes, int n_in,
                              void* d_out, int out_size) {
    const float4* ue  = (const float4*)d_in[0];   // user_emb  [100000,64] f32
    const float4* ie  = (const float4*)d_in[1];   // item_emb  [50000,64]  f32
    const float*  w   = (const float*) d_in[2];   // edge_weight [4.8M] f32
    const int*    src = (const int*)   d_in[3];   // edge_src [4.8M] i32
    const int*    dst = (const int*)   d_in[4];   // edge_dst [4.8M] i32
    float4*       out = (float4*)d_out;

    const int TB     = 256;
    const int gElem  = (NF4 + TB - 1) / TB;   // 9375
    const int gEdge  = (NE  + TB - 1) / TB;   // 18750
    const int gNode  = (NN  + TB - 1) / TB;   // 586

    k_init<<<gElem, TB>>>(ue, ie, out);

    // CSR build (per replay; graph-captured)
    k_hist     <<<gEdge, TB>>>(dst);
    k_scan_part<<<NB, SCAN_BS>>>();
    k_scan_tops<<<1, 256>>>();
    k_scan_add <<<gNode, TB>>>();
    k_fill     <<<gEdge, TB>>>(src, dst, w);

    // 3 pull layers; acc and final scale fused into epilogues.
    k_pull<<<gElem, TB>>>(out, 0, 0);   // x=A -> y=B ; out += y
    k_pull<<<gElem, TB>>>(out, 1, 0);   // x=B -> y=A ; out += y
    k_pull<<<gElem, TB>>>(out, 0, 1);   // x=A -> (out + y)/4
}